// round 2
// baseline (speedup 1.0000x reference)
#include <cuda_runtime.h>

#define NNODE 8000
#define TDIM 12
#define FDIM 5
#define RBLOCKS 32

// Scratch (device globals; no allocation allowed)
__device__ float g_partial[RBLOCKS][120];   // [block][0:60)=lhs1 (t*5+f), [60:120)=M (f*12+t')
__device__ float g_At2[144];                // At2[t'][t], row-major 12x12

// ---------------------------------------------------------------------------
// K1: per-block partial reductions over n of lhs1 and M.
//   lhs1[t,f] = sum_n U1[n] * x[n,t,f]
//   M[f,t']   = sum_n U2[f,n] * (sum_g U3[g]*x[n,t',g])
// 32 blocks x 256 threads, one n per thread, warp shuffle + shared tree.
// ---------------------------------------------------------------------------
__global__ void __launch_bounds__(256) k_reduce(
    const float* __restrict__ x, const float* __restrict__ U1,
    const float* __restrict__ U2, const float* __restrict__ U3)
{
    int n = blockIdx.x * blockDim.x + threadIdx.x;
    float v[120];
    if (n < NNODE) {
        float u3[5];
#pragma unroll
        for (int f = 0; f < 5; f++) u3[f] = U3[f];
        float u1 = U1[n];
        float rhs[12];
#pragma unroll
        for (int t = 0; t < 12; t++) rhs[t] = 0.f;
        const float4* xp = (const float4*)(x + (size_t)n * 60);
#pragma unroll
        for (int i = 0; i < 15; i++) {
            float4 q = xp[i];
            float e[4] = {q.x, q.y, q.z, q.w};
#pragma unroll
            for (int c = 0; c < 4; c++) {
                int j = 4 * i + c;          // j = t*5 + f
                v[j] = e[c] * u1;           // lhs1 contribution
                rhs[j / 5] += u3[j % 5] * e[c];
            }
        }
#pragma unroll
        for (int f = 0; f < 5; f++) {
            float u2 = U2[f * NNODE + n];
#pragma unroll
            for (int t = 0; t < 12; t++) v[60 + f * 12 + t] = u2 * rhs[t];
        }
    } else {
#pragma unroll
        for (int j = 0; j < 120; j++) v[j] = 0.f;
    }

    // warp tree reduce all 120 values
#pragma unroll
    for (int j = 0; j < 120; j++) {
#pragma unroll
        for (int off = 16; off > 0; off >>= 1)
            v[j] += __shfl_down_sync(0xffffffffu, v[j], off);
    }

    __shared__ float sred[8][120];
    int warp = threadIdx.x >> 5, lane = threadIdx.x & 31;
    if (lane == 0) {
#pragma unroll
        for (int j = 0; j < 120; j++) sred[warp][j] = v[j];
    }
    __syncthreads();
    if (threadIdx.x < 120) {
        float s = 0.f;
#pragma unroll
        for (int w = 0; w < 8; w++) s += sred[w][threadIdx.x];
        g_partial[blockIdx.x][threadIdx.x] = s;
    }
}

// ---------------------------------------------------------------------------
// K2: finish reductions, compute At2 = softmax_col( Ve @ sigmoid(lhs1@M + be) )
// 1 block x 256 threads. Everything is 12x12.
// ---------------------------------------------------------------------------
__global__ void __launch_bounds__(256) k_att(
    const float* __restrict__ be, const float* __restrict__ Ve)
{
    __shared__ float lhs1[60], M[60], S[144], E[144];
    int tid = threadIdx.x;
    if (tid < 120) {
        float s = 0.f;
#pragma unroll
        for (int b = 0; b < RBLOCKS; b++) s += g_partial[b][tid];
        if (tid < 60) lhs1[tid] = s;
        else          M[tid - 60] = s;
    }
    __syncthreads();
    if (tid < 144) {
        int i = tid / 12, j = tid % 12;
        float p = 0.f;
#pragma unroll
        for (int f = 0; f < 5; f++) p += lhs1[i * 5 + f] * M[f * 12 + j];
        p += be[tid];
        S[tid] = 1.f / (1.f + expf(-p));
    }
    __syncthreads();
    if (tid < 144) {
        int i = tid / 12, j = tid % 12;
        float e = 0.f;
#pragma unroll
        for (int k = 0; k < 12; k++) e += Ve[i * 12 + k] * S[k * 12 + j];
        E[tid] = e;
    }
    __syncthreads();
    if (tid < 144) {
        int j = tid % 12;
        float mx = -1e30f;
#pragma unroll
        for (int k = 0; k < 12; k++) mx = fmaxf(mx, E[k * 12 + j]);
        float sum = 0.f;
#pragma unroll
        for (int k = 0; k < 12; k++) sum += expf(E[k * 12 + j] - mx);
        g_At2[tid] = expf(E[tid] - mx) / sum;
    }
}

// ---------------------------------------------------------------------------
// K3: per node n:  x2[f][t] = sum_{t'} x[n,t',f] * At2[t'][t]
//                  y[o][t]  = b2[o] + sum_i sum_k w2[o,i,k]*x2[i][t+k-1]
// Output written in (o, n, t) row-major layout == flat output buffer.
// ---------------------------------------------------------------------------
__global__ void __launch_bounds__(128) k_main(
    const float* __restrict__ x, const float* __restrict__ w2,
    const float* __restrict__ b2, float* __restrict__ out)
{
    __shared__ float sA[144], sw[75], sb[5];
    int tid = threadIdx.x;
    for (int j = tid; j < 144; j += 128) sA[j] = g_At2[j];
    if (tid < 75) sw[tid] = w2[tid];
    if (tid < 5)  sb[tid] = b2[tid];
    __syncthreads();

    int n = blockIdx.x * blockDim.x + tid;
    if (n >= NNODE) return;

    float xr[60];
    const float4* xp = (const float4*)(x + (size_t)n * 60);
#pragma unroll
    for (int i = 0; i < 15; i++) {
        float4 q = xp[i];
        xr[4 * i + 0] = q.x; xr[4 * i + 1] = q.y;
        xr[4 * i + 2] = q.z; xr[4 * i + 3] = q.w;
    }

    float x2[5][12];
#pragma unroll
    for (int f = 0; f < 5; f++)
#pragma unroll
        for (int t = 0; t < 12; t++) x2[f][t] = 0.f;

#pragma unroll
    for (int tp = 0; tp < 12; tp++) {
        float a[12];
#pragma unroll
        for (int t = 0; t < 12; t++) a[t] = sA[tp * 12 + t];
#pragma unroll
        for (int f = 0; f < 5; f++) {
            float xv = xr[tp * 5 + f];
#pragma unroll
            for (int t = 0; t < 12; t++) x2[f][t] += xv * a[t];
        }
    }

#pragma unroll
    for (int o = 0; o < 5; o++) {
        float wr[15];
#pragma unroll
        for (int q = 0; q < 15; q++) wr[q] = sw[o * 15 + q];
        float bo = sb[o];
        float y[12];
#pragma unroll
        for (int t = 0; t < 12; t++) {
            float acc = bo;
#pragma unroll
            for (int i = 0; i < 5; i++) {
                if (t > 0)  acc += wr[i * 3 + 0] * x2[i][t - 1];
                acc += wr[i * 3 + 1] * x2[i][t];
                if (t < 11) acc += wr[i * 3 + 2] * x2[i][t + 1];
            }
            y[t] = acc;
        }
        float4* op = (float4*)(out + (size_t)o * NNODE * TDIM + (size_t)n * TDIM);
        op[0] = make_float4(y[0], y[1], y[2],  y[3]);
        op[1] = make_float4(y[4], y[5], y[6],  y[7]);
        op[2] = make_float4(y[8], y[9], y[10], y[11]);
    }
}

extern "C" void kernel_launch(void* const* d_in, const int* in_sizes, int n_in,
                              void* d_out, int out_size)
{
    // metadata order: x, adj, U1_1, U2_1, U3_1, be_1, Ve_1,
    //                 U1_2, U2_2, U3_2, be_2, Ve_2,
    //                 conv1_w, conv1_b, conv2_w, conv2_b, W_hgc, b_hgc
    const float* x  = (const float*)d_in[0];
    const float* U1 = (const float*)d_in[7];
    const float* U2 = (const float*)d_in[8];
    const float* U3 = (const float*)d_in[9];
    const float* be = (const float*)d_in[10];
    const float* Ve = (const float*)d_in[11];
    const float* w2 = (const float*)d_in[14];
    const float* b2 = (const float*)d_in[15];
    float* out = (float*)d_out;

    k_reduce<<<RBLOCKS, 256>>>(x, U1, U2, U3);
    k_att<<<1, 256>>>(be, Ve);
    k_main<<<(NNODE + 127) / 128, 128>>>(x, w2, b2, out);
}